// round 16
// baseline (speedup 1.0000x reference)
#include <cuda_runtime.h>
#include <cuda_fp16.h>
#include <cstdint>
#include <cstddef>

#define NSAMP 16384
#define HID   512
#define DIN   128
#define EOBS  4096
#define KOBS  40
#define DTF   0.05f

#define MODE_TANH    0
#define MODE_EULER   1
#define MODE_RELU_G  2
#define MODE_RNN     3
#define MODE_LOSS    5

// ------------------------------------------------------------------
// Device scratch (no allocations allowed)
// ------------------------------------------------------------------
__device__ __half g_h_hi[(size_t)NSAMP*HID];
__device__ __half g_h_lo[(size_t)NSAMP*HID];
__device__ __half g_t_hi[(size_t)NSAMP*HID];
__device__ __half g_p1_hi[(size_t)EOBS*HID];
__device__ __half g_hn_hi[(size_t)EOBS*HID];
__device__ __half g_hn_lo[(size_t)EOBS*HID];
__device__ __half g_X_hi[(size_t)KOBS*EOBS*DIN];

__device__ __half g_Wih_h[HID*DIN];
__device__ __half g_Whh_h[HID*HID];
__device__ __half g_Wo1_h[HID*HID];
__device__ __half g_Wo2_h[HID*HID];
__device__ __half g_Wp1_h[HID*HID];
__device__ __half g_Wp2_h[DIN*HID];

__device__ unsigned g_flag[128];    // per-row-block TANH completion counters

__device__ double g_loss;
__device__ double g_totm;

// ------------------------------------------------------------------
// PTX helpers (portable sm_80+)
// ------------------------------------------------------------------
__device__ __forceinline__ uint32_t smem_u32(const void* p) {
    uint32_t a;
    asm("{ .reg .u64 t; cvta.to.shared.u64 t, %1; cvt.u32.u64 %0, t; }" : "=r"(a) : "l"(p));
    return a;
}
__device__ __forceinline__ void cp16(uint32_t dst, const void* src) {
    asm volatile("cp.async.cg.shared.global [%0], [%1], 16;" :: "r"(dst), "l"(src) : "memory");
}
__device__ __forceinline__ void cp_commit() {
    asm volatile("cp.async.commit_group;" ::: "memory");
}
template<int N>
__device__ __forceinline__ void cp_wait() {
    asm volatile("cp.async.wait_group %0;" :: "n"(N) : "memory");
}
__device__ __forceinline__ void ldm4(uint32_t* r, uint32_t addr) {
    asm volatile("ldmatrix.sync.aligned.m8n8.x4.shared.b16 {%0,%1,%2,%3}, [%4];"
                 : "=r"(r[0]), "=r"(r[1]), "=r"(r[2]), "=r"(r[3]) : "r"(addr));
}
__device__ __forceinline__ void mma16816(float* d, const uint32_t* a, const uint32_t* b) {
    asm volatile(
        "mma.sync.aligned.m16n8k16.row.col.f32.f16.f16.f32 "
        "{%0,%1,%2,%3}, {%4,%5,%6,%7}, {%8,%9}, {%0,%1,%2,%3};"
        : "+f"(d[0]), "+f"(d[1]), "+f"(d[2]), "+f"(d[3])
        : "r"(a[0]), "r"(a[1]), "r"(a[2]), "r"(a[3]), "r"(b[0]), "r"(b[1]));
}
__device__ __forceinline__ uint32_t sw128(uint32_t off) { return off ^ ((off >> 3) & 0x70); }

// SMEM plan: [pad <=1024][3 stages x 2 mats x 16KB][ctrl 1KB]
#define TILE_BYTES   16384
#define STAGE_BYTES  32768
#define NSTAGE       3
#define SMEM_DYN     (NSTAGE*STAGE_BYTES + 1024 + 1024)

// ------------------------------------------------------------------
// GEMM body (R12 core, proven 34us): C[M,NOUT] = epi( A[M,K] @ W[NOUT,K]^T )
// ------------------------------------------------------------------
template<int MODE, int KDIM, int NOUT>
__device__ __forceinline__
void gemm_body(const __half* __restrict__ Ah,  const __half* __restrict__ Bh,
               const __half* __restrict__ A2h, const __half* __restrict__ B2h,
               const float* __restrict__ bias, const float* __restrict__ bias2,
               const __half* __restrict__ Cin_hi, const __half* __restrict__ Cin_lo,
               __half* __restrict__ Ohi, __half* __restrict__ Olo,
               const int* __restrict__ gidx,
               const float* __restrict__ Xo, const float* __restrict__ Mo)
{
    constexpr int  NC     = KDIM / 64;
    constexpr bool GATHER = (MODE == MODE_RELU_G || MODE == MODE_RNN);

    extern __shared__ char smraw[];
    const uint32_t sbase = smem_u32(smraw);
    const uint32_t tbase = (sbase + 1023u) & ~1023u;
    char* ctrlp = smraw + (tbase - sbase) + NSTAGE * STAGE_BYTES;
    int*   sIdx = (int*)ctrlp;
    float* redL = (float*)(ctrlp + 512);
    float* redM = (float*)(ctrlp + 544);

    const int tid = threadIdx.x, wid = tid >> 5, lid = tid & 31;
    const int rowbase = blockIdx.y * 128;
    const int colbase = blockIdx.x * 128;
    const int wr = wid & 3, wc = wid >> 2;

    if (GATHER) {
        if (tid < 128) sIdx[tid] = gidx[rowbase + tid];
        __syncthreads();
    }

    auto load_chunk = [&](int kc, int stage) {
        const uint32_t sb = tbase + (uint32_t)stage * STAGE_BYTES;
#pragma unroll
        for (int u = 0; u < 8; u++) {
            const int mat = u >> 2;
            const int rem = (u & 3) * 256 + tid;
            const int row = rem >> 3;
            const int un  = rem & 7;
            const __half* src;
            if constexpr (MODE == MODE_RNN) {
                if (mat == 0) {
                    if (kc < 2) src = Ah  + (size_t)(rowbase + row) * DIN + kc * 64 + un * 8;
                    else        src = A2h + (size_t)sIdx[row] * HID + (kc - 2) * 64 + un * 8;
                } else {
                    if (kc < 2) src = Bh  + (size_t)(colbase + row) * DIN + kc * 64 + un * 8;
                    else        src = B2h + (size_t)(colbase + row) * HID + (kc - 2) * 64 + un * 8;
                }
            } else {
                if (mat == 0) {
                    int rg = GATHER ? sIdx[row] : (rowbase + row);
                    src = Ah + (size_t)rg * KDIM + kc * 64 + un * 8;
                } else {
                    src = Bh + (size_t)(colbase + row) * KDIM + kc * 64 + un * 8;
                }
            }
            cp16(sb + (uint32_t)mat * TILE_BYTES + sw128((uint32_t)(row * 128 + un * 16)), src);
        }
    };

    float acc[2][8][4];
#pragma unroll
    for (int i = 0; i < 2; i++)
#pragma unroll
        for (int j = 0; j < 8; j++)
#pragma unroll
            for (int q = 0; q < 4; q++) acc[i][j][q] = 0.f;

    auto compute = [&](int stage) {
        const uint32_t sb = tbase + (uint32_t)stage * STAGE_BYTES;
#pragma unroll
        for (int k16 = 0; k16 < 4; k16++) {
            uint32_t ah[2][4];
#pragma unroll
            for (int mi = 0; mi < 2; mi++) {
                uint32_t off = (uint32_t)((wr * 32 + mi * 16 + (lid & 15)) * 128
                                          + k16 * 32 + (lid >> 4) * 16);
                ldm4(ah[mi], sb + sw128(off));
            }
            uint32_t bh[4][4];
#pragma unroll
            for (int nb = 0; nb < 4; nb++) {
                uint32_t off = (uint32_t)((wc * 64 + nb * 16 + (lid & 7) + ((lid >> 4) & 1) * 8) * 128
                                          + k16 * 32 + ((lid >> 3) & 1) * 16);
                ldm4(bh[nb], sb + TILE_BYTES + sw128(off));
            }
#pragma unroll
            for (int mi = 0; mi < 2; mi++)
#pragma unroll
                for (int na = 0; na < 8; na++)
                    mma16816(acc[mi][na], ah[mi], &bh[na >> 1][(na & 1) * 2]);
        }
    };

    // single-sync multistage mainloop
    load_chunk(0, 0); cp_commit();
    load_chunk(1, 1); cp_commit();
#pragma unroll 1
    for (int c = 0; c < NC; c++) {
        if (c + 1 < NC) cp_wait<1>();
        else            cp_wait<0>();
        __syncthreads();
        if (c + 2 < NC) { load_chunk(c + 2, (c + 2) % NSTAGE); cp_commit(); }
        compute(c % NSTAGE);
    }

    float lsum = 0.f, msum = 0.f;
#pragma unroll
    for (int mi = 0; mi < 2; mi++) {
#pragma unroll
        for (int hh = 0; hh < 2; hh++) {
            const int row = rowbase + wr * 32 + mi * 16 + (lid >> 2) + hh * 8;
#pragma unroll
            for (int na = 0; na < 8; na++) {
                const int c = colbase + wc * 64 + na * 8 + (lid & 3) * 2;
                float v0 = acc[mi][na][hh * 2 + 0];
                float v1 = acc[mi][na][hh * 2 + 1];
                if constexpr (MODE == MODE_LOSS) {
                    float2 bb = *(const float2*)(bias + c);
                    float2 xx = *(const float2*)(Xo + (size_t)row * NOUT + c);
                    float2 mm = *(const float2*)(Mo + (size_t)row * NOUT + c);
                    lsum += fabsf(xx.x - (v0 + bb.x)) * mm.x + fabsf(xx.y - (v1 + bb.y)) * mm.y;
                    msum += mm.x + mm.y;
                } else {
                    if constexpr (MODE == MODE_TANH) {
                        float2 bb = *(const float2*)(bias + c);
                        v0 = tanhf(v0 + bb.x); v1 = tanhf(v1 + bb.y);
                    } else if constexpr (MODE == MODE_EULER) {
                        float2 bb = *(const float2*)(bias + c);
                        float2 chv = __half22float2(*(const __half2*)(Cin_hi + (size_t)row * NOUT + c));
                        float2 clv = __half22float2(*(const __half2*)(Cin_lo + (size_t)row * NOUT + c));
                        v0 = (chv.x + clv.x) + DTF * (v0 + bb.x);
                        v1 = (chv.y + clv.y) + DTF * (v1 + bb.y);
                    } else if constexpr (MODE == MODE_RELU_G) {
                        float2 bb = *(const float2*)(bias + c);
                        v0 += bb.x; v1 += bb.y;
                        v0 = v0 > 0.f ? v0 : 0.f; v1 = v1 > 0.f ? v1 : 0.f;
                    } else if constexpr (MODE == MODE_RNN) {
                        float2 b1 = *(const float2*)(bias + c);
                        float2 b2 = *(const float2*)(bias2 + c);
                        v0 = tanhf(v0 + b1.x + b2.x);
                        v1 = tanhf(v1 + b1.y + b2.y);
                    }
                    __half h0 = __float2half_rn(v0);
                    __half h1 = __float2half_rn(v1);
                    *(__half2*)(Ohi + (size_t)row * NOUT + c) = __halves2half2(h0, h1);
                    if constexpr (MODE == MODE_EULER || MODE == MODE_RNN) {
                        __half l0 = __float2half_rn(v0 - __half2float(h0));
                        __half l1 = __float2half_rn(v1 - __half2float(h1));
                        *(__half2*)(Olo + (size_t)row * NOUT + c) = __halves2half2(l0, l1);
                    }
                }
            }
        }
    }

    if constexpr (MODE == MODE_LOSS) {
#pragma unroll
        for (int o = 16; o > 0; o >>= 1) {
            lsum += __shfl_xor_sync(0xFFFFFFFFu, lsum, o);
            msum += __shfl_xor_sync(0xFFFFFFFFu, msum, o);
        }
        if (lid == 0) { redL[wid] = lsum; redM[wid] = msum; }
        __syncthreads();
        if (tid == 0) {
            float L = 0.f, Mt = 0.f;
#pragma unroll
            for (int i = 0; i < 8; i++) { L += redL[i]; Mt += redM[i]; }
            atomicAdd(&g_loss, (double)L);
            atomicAdd(&g_totm, (double)Mt);
        }
    }
}

// ---- fused Euler pair: z=0 TANH (producer, flags row-blocks),
//                        z=1 EULER (consumer, spins on its row-block) ----
__global__ __launch_bounds__(256, 2)
void euler_pair_kernel(__half* __restrict__ h_hi, __half* __restrict__ h_lo,
                       __half* __restrict__ t_hi,
                       const __half* __restrict__ Wo1h, const __half* __restrict__ Wo2h,
                       const float* __restrict__ bo1, const float* __restrict__ bo2,
                       unsigned epoch)
{
    if (blockIdx.z == 0) {
        gemm_body<MODE_TANH, HID, HID>(h_hi, Wo1h, nullptr, nullptr, bo1, nullptr,
                                       nullptr, nullptr, t_hi, nullptr, nullptr, nullptr, nullptr);
        __threadfence();                 // each thread orders its own t stores
        __syncthreads();                 // all threads' fences done
        if (threadIdx.x == 0) atomicAdd(&g_flag[blockIdx.y], 1u);
    } else {
        // wait for all 4 TANH col-tiles of this row-block (target = 4*epoch, monotone)
        if (threadIdx.x == 0) {
            const unsigned target = 4u * epoch;
            while (atomicAdd(&g_flag[blockIdx.y], 0u) < target) { }
            __threadfence();
        }
        __syncthreads();
        gemm_body<MODE_EULER, HID, HID>(t_hi, Wo2h, nullptr, nullptr, bo2, nullptr,
                                        h_hi, h_lo, h_hi, h_lo, nullptr, nullptr, nullptr);
    }
}

// ---- fused launch A: z=0 RELU_G, z=1 RNN (independent) ----
__global__ __launch_bounds__(256, 2)
void obs_a_kernel(const __half* __restrict__ h_hi,
                  const __half* __restrict__ Wp1h, const float* __restrict__ bp1,
                  __half* __restrict__ p1_hi,
                  const __half* __restrict__ Xhs,
                  const __half* __restrict__ Wih, const __half* __restrict__ Whh,
                  const float* __restrict__ b_ih, const float* __restrict__ b_hh,
                  __half* __restrict__ hn_hi, __half* __restrict__ hn_lo,
                  const int* __restrict__ is)
{
    if (blockIdx.z == 0)
        gemm_body<MODE_RELU_G, HID, HID>(h_hi, Wp1h, nullptr, nullptr, bp1, nullptr,
                                         nullptr, nullptr, p1_hi, nullptr, is, nullptr, nullptr);
    else
        gemm_body<MODE_RNN, 640, HID>(Xhs, Wih, h_hi, Whh, b_ih, b_hh,
                                      nullptr, nullptr, hn_hi, hn_lo, is, nullptr, nullptr);
}

// ---- fused launch B: z=0 LOSS (x==0 only), z=1 scatter (128 CTAs) ----
__global__ __launch_bounds__(256, 2)
void obs_b_kernel(const __half* __restrict__ p1_hi,
                  const __half* __restrict__ Wp2h, const float* __restrict__ bp2,
                  const float* __restrict__ Xs, const float* __restrict__ Ms,
                  const int* __restrict__ is)
{
    if (blockIdx.z == 0) {
        if (blockIdx.x != 0) return;
        gemm_body<MODE_LOSS, HID, DIN>(p1_hi, Wp2h, nullptr, nullptr, bp2, nullptr,
                                       nullptr, nullptr, nullptr, nullptr, nullptr, Xs, Ms);
    } else {
        const int tid = threadIdx.x;
        const int rowbase = (blockIdx.y * 4 + blockIdx.x) * 32;
#pragma unroll 1
        for (int i = tid; i < 32 * 64; i += 256) {
            int r = i >> 6, q = i & 63;
            size_t dst = (size_t)is[rowbase + r] * HID;
            size_t src = (size_t)(rowbase + r) * HID;
            ((uint4*)(g_h_hi + dst))[q] = ((const uint4*)(g_hn_hi + src))[q];
            ((uint4*)(g_h_lo + dst))[q] = ((const uint4*)(g_hn_lo + src))[q];
        }
    }
}

// ------------------------------------------------------------------
// Small kernels
// ------------------------------------------------------------------
__global__ void init_kernel()
{
    size_t i = (size_t)blockIdx.x * blockDim.x + threadIdx.x;   // over NSAMP*HID/8
    ((uint4*)g_h_hi)[i] = make_uint4(0, 0, 0, 0);
    ((uint4*)g_h_lo)[i] = make_uint4(0, 0, 0, 0);
    if (blockIdx.x == 0 && threadIdx.x < 128) g_flag[threadIdx.x] = 0u;
    if (i == 0) { g_loss = 0.0; g_totm = 0.0; }
}

__global__ void conv_hi_kernel(const float* __restrict__ src,
                               __half* __restrict__ hi, int n4)
{
    int i = blockIdx.x * blockDim.x + threadIdx.x;
    if (i >= n4) return;
    float4 s = ((const float4*)src)[i];
    ((__half2*)hi)[i * 2]     = __halves2half2(__float2half_rn(s.x), __float2half_rn(s.y));
    ((__half2*)hi)[i * 2 + 1] = __halves2half2(__float2half_rn(s.z), __float2half_rn(s.w));
}

__global__ void conv_weights_kernel(const float* __restrict__ W_ih, const float* __restrict__ W_hh,
                                    const float* __restrict__ Wo1,  const float* __restrict__ Wo2,
                                    const float* __restrict__ Wp1,  const float* __restrict__ Wp2)
{
    int i = blockIdx.x * blockDim.x + threadIdx.x;   // float4 index, total 294912
    const float* src; __half* dst; int base;
    if      (i <  16384) { src = W_ih; dst = g_Wih_h; base = 0;      }
    else if (i <  81920) { src = W_hh; dst = g_Whh_h; base = 16384;  }
    else if (i < 147456) { src = Wo1;  dst = g_Wo1_h; base = 81920;  }
    else if (i < 212992) { src = Wo2;  dst = g_Wo2_h; base = 147456; }
    else if (i < 278528) { src = Wp1;  dst = g_Wp1_h; base = 212992; }
    else if (i < 294912) { src = Wp2;  dst = g_Wp2_h; base = 278528; }
    else return;
    int j = i - base;
    float4 s = ((const float4*)src)[j];
    ((__half2*)dst)[j * 2]     = __halves2half2(__float2half_rn(s.x), __float2half_rn(s.y));
    ((__half2*)dst)[j * 2 + 1] = __halves2half2(__float2half_rn(s.z), __float2half_rn(s.w));
}

__global__ void final_kernel(float* __restrict__ out)
{
    out[0] = (float)g_loss;
    out[1] = (float)(g_loss / g_totm);
}

// ------------------------------------------------------------------
// Launch
// ------------------------------------------------------------------
extern "C" void kernel_launch(void* const* d_in, const int* in_sizes, int n_in,
                              void* d_out, int out_size)
{
    const float* X    = (const float*)d_in[0];
    const float* Mm   = (const float*)d_in[1];
    const int*   bidx = (const int*)  d_in[2];
    const float* W_ih = (const float*)d_in[3];
    const float* b_ih = (const float*)d_in[4];
    const float* W_hh = (const float*)d_in[5];
    const float* b_hh = (const float*)d_in[6];
    const float* Wo1  = (const float*)d_in[7];
    const float* bo1  = (const float*)d_in[8];
    const float* Wo2  = (const float*)d_in[9];
    const float* bo2  = (const float*)d_in[10];
    const float* Wp1  = (const float*)d_in[11];
    const float* bp1  = (const float*)d_in[12];
    const float* Wp2  = (const float*)d_in[13];
    const float* bp2  = (const float*)d_in[14];

    __half *h_hi, *h_lo, *t_hi, *p1_hi, *hn_hi, *hn_lo, *X_hi;
    __half *Wih, *Whh, *Wo1h, *Wo2h, *Wp1h, *Wp2h;
    cudaGetSymbolAddress((void**)&h_hi,  g_h_hi);   cudaGetSymbolAddress((void**)&h_lo,  g_h_lo);
    cudaGetSymbolAddress((void**)&t_hi,  g_t_hi);
    cudaGetSymbolAddress((void**)&p1_hi, g_p1_hi);
    cudaGetSymbolAddress((void**)&hn_hi, g_hn_hi);  cudaGetSymbolAddress((void**)&hn_lo, g_hn_lo);
    cudaGetSymbolAddress((void**)&X_hi,  g_X_hi);
    cudaGetSymbolAddress((void**)&Wih,  g_Wih_h);
    cudaGetSymbolAddress((void**)&Whh,  g_Whh_h);
    cudaGetSymbolAddress((void**)&Wo1h, g_Wo1_h);
    cudaGetSymbolAddress((void**)&Wo2h, g_Wo2_h);
    cudaGetSymbolAddress((void**)&Wp1h, g_Wp1_h);
    cudaGetSymbolAddress((void**)&Wp2h, g_Wp2_h);

    cudaFuncSetAttribute(euler_pair_kernel, cudaFuncAttributeMaxDynamicSharedMemorySize, SMEM_DYN);
    cudaFuncSetAttribute(obs_a_kernel,      cudaFuncAttributeMaxDynamicSharedMemorySize, SMEM_DYN);
    cudaFuncSetAttribute(obs_b_kernel,      cudaFuncAttributeMaxDynamicSharedMemorySize, SMEM_DYN);

    // launch 0: zero state + accumulators + flags
    init_kernel<<<(NSAMP * HID / 8) / 256, 256>>>();
    // launch 1: convert X
    conv_hi_kernel<<<(KOBS*EOBS*DIN/4 + 255)/256, 256>>>(X, X_hi, KOBS*EOBS*DIN/4);
    // launch 2: convert all 6 weight matrices
    conv_weights_kernel<<<1152, 256>>>(W_ih, W_hh, Wo1, Wo2, Wp1, Wp2);

    const dim3 gPair (HID / 128, NSAMP / 128, 2);   // (4, 128, 2): TANH -> EULER overlapped
    const dim3 gObsA (HID / 128, EOBS  / 128, 2);   // (4, 32, 2): RELU_G || RNN
    const dim3 gObsB (4,         EOBS  / 128, 2);   // (4, 32, 2): LOSS(x==0) || scatter

    unsigned epoch = 0;
    for (int s = 0; s < KOBS; s++) {
        const float* Xs = X  + (size_t)s * EOBS * DIN;
        const float* Ms = Mm + (size_t)s * EOBS * DIN;
        const int*   is = bidx + (size_t)s * EOBS;
        const __half* Xhs = X_hi + (size_t)s * EOBS * DIN;

        for (int e = 0; e < 2; e++) {
            epoch++;
            // fused Euler step: TANH producer row-blocks -> EULER consumers (flag spin)
            euler_pair_kernel<<<gPair, 256, SMEM_DYN>>>(
                h_hi, h_lo, t_hi, Wo1h, Wo2h, bo1, bo2, epoch);
        }
        // RELU_G || RNN  (independent; both read h, write p1 / hn)
        obs_a_kernel<<<gObsA, 256, SMEM_DYN>>>(
            h_hi, Wp1h, bp1, p1_hi, Xhs, Wih, Whh, b_ih, b_hh, hn_hi, hn_lo, is);
        // LOSS || scatter  (independent; scatter legal: RNN finished last launch)
        obs_b_kernel<<<gObsB, 256, SMEM_DYN>>>(p1_hi, Wp2h, bp2, Xs, Ms, is);
    }
    // prop_to_end Euler steps are output-invariant -> skipped.

    final_kernel<<<1, 1>>>((float*)d_out);
}

// round 17
// speedup vs baseline: 6.2711x; 6.2711x over previous
#include <cuda_runtime.h>
#include <cuda_fp16.h>
#include <cstdint>
#include <cstddef>

#define NSAMP 16384
#define HID   512
#define DIN   128
#define EOBS  4096
#define KOBS  40
#define DTF   0.05f

#define MODE_TANH    0
#define MODE_EULER   1
#define MODE_RELU_G  2
#define MODE_RNN     3
#define MODE_LOSS    5

// ------------------------------------------------------------------
// Device scratch (no allocations allowed)
// ------------------------------------------------------------------
__device__ __half g_h_hi[(size_t)NSAMP*HID];   // state hi
__device__ __half g_h_lo[(size_t)NSAMP*HID];   // state lo (precision carrier)
__device__ __half g_t_hi[(size_t)NSAMP*HID];
__device__ __half g_p1_hi[(size_t)EOBS*HID];
__device__ __half g_hn_hi[(size_t)EOBS*HID];
__device__ __half g_hn_lo[(size_t)EOBS*HID];
__device__ __half g_X_hi[(size_t)KOBS*EOBS*DIN];

__device__ __half g_Wih_h[HID*DIN];
__device__ __half g_Whh_h[HID*HID];
__device__ __half g_Wo1_h[HID*HID];
__device__ __half g_Wo2_h[HID*HID];
__device__ __half g_Wp1_h[HID*HID];
__device__ __half g_Wp2_h[DIN*HID];

__device__ double g_loss;
__device__ double g_totm;

// ------------------------------------------------------------------
// PTX helpers (portable sm_80+)
// ------------------------------------------------------------------
__device__ __forceinline__ uint32_t smem_u32(const void* p) {
    uint32_t a;
    asm("{ .reg .u64 t; cvta.to.shared.u64 t, %1; cvt.u32.u64 %0, t; }" : "=r"(a) : "l"(p));
    return a;
}
__device__ __forceinline__ void cp16(uint32_t dst, const void* src) {
    asm volatile("cp.async.cg.shared.global [%0], [%1], 16;" :: "r"(dst), "l"(src) : "memory");
}
__device__ __forceinline__ void cp_commit() {
    asm volatile("cp.async.commit_group;" ::: "memory");
}
template<int N>
__device__ __forceinline__ void cp_wait() {
    asm volatile("cp.async.wait_group %0;" :: "n"(N) : "memory");
}
__device__ __forceinline__ void ldm4(uint32_t* r, uint32_t addr) {
    asm volatile("ldmatrix.sync.aligned.m8n8.x4.shared.b16 {%0,%1,%2,%3}, [%4];"
                 : "=r"(r[0]), "=r"(r[1]), "=r"(r[2]), "=r"(r[3]) : "r"(addr));
}
__device__ __forceinline__ void mma16816(float* d, const uint32_t* a, const uint32_t* b) {
    asm volatile(
        "mma.sync.aligned.m16n8k16.row.col.f32.f16.f16.f32 "
        "{%0,%1,%2,%3}, {%4,%5,%6,%7}, {%8,%9}, {%0,%1,%2,%3};"
        : "+f"(d[0]), "+f"(d[1]), "+f"(d[2]), "+f"(d[3])
        : "r"(a[0]), "r"(a[1]), "r"(a[2]), "r"(a[3]), "r"(b[0]), "r"(b[1]));
}
__device__ __forceinline__ uint32_t sw128(uint32_t off) { return off ^ ((off >> 3) & 0x70); }

// SMEM plan: [pad <=1024][3 stages x 2 mats x 16KB][ctrl 1KB]
#define TILE_BYTES   16384
#define STAGE_BYTES  32768
#define NSTAGE       3
#define SMEM_DYN     (NSTAGE*STAGE_BYTES + 1024 + 1024)

// ------------------------------------------------------------------
// GEMM body: C[M,NOUT] = epi( A[M,K] @ W[NOUT,K]^T )   [R12 core, proven 34us]
// fp16 inputs, fp32 accumulators. CTA 128x128, 8 warps (4x2), warp tile 32x64.
// Single __syncthreads per K-chunk multistage (NSTAGE=3, race-free).
// MODE_RNN: K=640 concatenation  [X(128) | h_gathered(512)] @ [Wih | Whh]^T
// ------------------------------------------------------------------
template<int MODE, int KDIM, int NOUT>
__device__ __forceinline__
void gemm_body(const __half* __restrict__ Ah,  const __half* __restrict__ Bh,
               const __half* __restrict__ A2h, const __half* __restrict__ B2h,
               const float* __restrict__ bias, const float* __restrict__ bias2,
               const __half* __restrict__ Cin_hi, const __half* __restrict__ Cin_lo,
               __half* __restrict__ Ohi, __half* __restrict__ Olo,
               const int* __restrict__ gidx,
               const float* __restrict__ Xo, const float* __restrict__ Mo)
{
    constexpr int  NC     = KDIM / 64;
    constexpr bool GATHER = (MODE == MODE_RELU_G || MODE == MODE_RNN);

    extern __shared__ char smraw[];
    const uint32_t sbase = smem_u32(smraw);
    const uint32_t tbase = (sbase + 1023u) & ~1023u;
    char* ctrlp = smraw + (tbase - sbase) + NSTAGE * STAGE_BYTES;
    int*   sIdx = (int*)ctrlp;
    float* redL = (float*)(ctrlp + 512);
    float* redM = (float*)(ctrlp + 544);

    const int tid = threadIdx.x, wid = tid >> 5, lid = tid & 31;
    const int rowbase = blockIdx.y * 128;
    const int colbase = blockIdx.x * 128;
    const int wr = wid & 3, wc = wid >> 2;

    if (GATHER) {
        if (tid < 128) sIdx[tid] = gidx[rowbase + tid];
        __syncthreads();
    }

    auto load_chunk = [&](int kc, int stage) {
        const uint32_t sb = tbase + (uint32_t)stage * STAGE_BYTES;
#pragma unroll
        for (int u = 0; u < 8; u++) {
            const int mat = u >> 2;
            const int rem = (u & 3) * 256 + tid;
            const int row = rem >> 3;
            const int un  = rem & 7;
            const __half* src;
            if constexpr (MODE == MODE_RNN) {
                if (mat == 0) {
                    if (kc < 2) src = Ah  + (size_t)(rowbase + row) * DIN + kc * 64 + un * 8;
                    else        src = A2h + (size_t)sIdx[row] * HID + (kc - 2) * 64 + un * 8;
                } else {
                    if (kc < 2) src = Bh  + (size_t)(colbase + row) * DIN + kc * 64 + un * 8;
                    else        src = B2h + (size_t)(colbase + row) * HID + (kc - 2) * 64 + un * 8;
                }
            } else {
                if (mat == 0) {
                    int rg = GATHER ? sIdx[row] : (rowbase + row);
                    src = Ah + (size_t)rg * KDIM + kc * 64 + un * 8;
                } else {
                    src = Bh + (size_t)(colbase + row) * KDIM + kc * 64 + un * 8;
                }
            }
            cp16(sb + (uint32_t)mat * TILE_BYTES + sw128((uint32_t)(row * 128 + un * 16)), src);
        }
    };

    float acc[2][8][4];
#pragma unroll
    for (int i = 0; i < 2; i++)
#pragma unroll
        for (int j = 0; j < 8; j++)
#pragma unroll
            for (int q = 0; q < 4; q++) acc[i][j][q] = 0.f;

    auto compute = [&](int stage) {
        const uint32_t sb = tbase + (uint32_t)stage * STAGE_BYTES;
#pragma unroll
        for (int k16 = 0; k16 < 4; k16++) {
            uint32_t ah[2][4];
#pragma unroll
            for (int mi = 0; mi < 2; mi++) {
                uint32_t off = (uint32_t)((wr * 32 + mi * 16 + (lid & 15)) * 128
                                          + k16 * 32 + (lid >> 4) * 16);
                ldm4(ah[mi], sb + sw128(off));
            }
            uint32_t bh[4][4];
#pragma unroll
            for (int nb = 0; nb < 4; nb++) {
                uint32_t off = (uint32_t)((wc * 64 + nb * 16 + (lid & 7) + ((lid >> 4) & 1) * 8) * 128
                                          + k16 * 32 + ((lid >> 3) & 1) * 16);
                ldm4(bh[nb], sb + TILE_BYTES + sw128(off));
            }
#pragma unroll
            for (int mi = 0; mi < 2; mi++)
#pragma unroll
                for (int na = 0; na < 8; na++)
                    mma16816(acc[mi][na], ah[mi], &bh[na >> 1][(na & 1) * 2]);
        }
    };

    // single-sync multistage mainloop
    load_chunk(0, 0); cp_commit();
    load_chunk(1, 1); cp_commit();
#pragma unroll 1
    for (int c = 0; c < NC; c++) {
        if (c + 1 < NC) cp_wait<1>();
        else            cp_wait<0>();
        __syncthreads();
        if (c + 2 < NC) { load_chunk(c + 2, (c + 2) % NSTAGE); cp_commit(); }
        compute(c % NSTAGE);
    }

    float lsum = 0.f, msum = 0.f;
#pragma unroll
    for (int mi = 0; mi < 2; mi++) {
#pragma unroll
        for (int hh = 0; hh < 2; hh++) {
            const int row = rowbase + wr * 32 + mi * 16 + (lid >> 2) + hh * 8;
#pragma unroll
            for (int na = 0; na < 8; na++) {
                const int c = colbase + wc * 64 + na * 8 + (lid & 3) * 2;
                float v0 = acc[mi][na][hh * 2 + 0];
                float v1 = acc[mi][na][hh * 2 + 1];
                if constexpr (MODE == MODE_LOSS) {
                    float2 bb = *(const float2*)(bias + c);
                    float2 xx = *(const float2*)(Xo + (size_t)row * NOUT + c);
                    float2 mm = *(const float2*)(Mo + (size_t)row * NOUT + c);
                    lsum += fabsf(xx.x - (v0 + bb.x)) * mm.x + fabsf(xx.y - (v1 + bb.y)) * mm.y;
                    msum += mm.x + mm.y;
                } else {
                    if constexpr (MODE == MODE_TANH) {
                        float2 bb = *(const float2*)(bias + c);
                        v0 = tanhf(v0 + bb.x); v1 = tanhf(v1 + bb.y);
                    } else if constexpr (MODE == MODE_EULER) {
                        float2 bb = *(const float2*)(bias + c);
                        float2 chv = __half22float2(*(const __half2*)(Cin_hi + (size_t)row * NOUT + c));
                        float2 clv = __half22float2(*(const __half2*)(Cin_lo + (size_t)row * NOUT + c));
                        v0 = (chv.x + clv.x) + DTF * (v0 + bb.x);
                        v1 = (chv.y + clv.y) + DTF * (v1 + bb.y);
                    } else if constexpr (MODE == MODE_RELU_G) {
                        float2 bb = *(const float2*)(bias + c);
                        v0 += bb.x; v1 += bb.y;
                        v0 = v0 > 0.f ? v0 : 0.f; v1 = v1 > 0.f ? v1 : 0.f;
                    } else if constexpr (MODE == MODE_RNN) {
                        float2 b1 = *(const float2*)(bias + c);
                        float2 b2 = *(const float2*)(bias2 + c);
                        v0 = tanhf(v0 + b1.x + b2.x);
                        v1 = tanhf(v1 + b1.y + b2.y);
                    }
                    __half h0 = __float2half_rn(v0);
                    __half h1 = __float2half_rn(v1);
                    *(__half2*)(Ohi + (size_t)row * NOUT + c) = __halves2half2(h0, h1);
                    if constexpr (MODE == MODE_EULER || MODE == MODE_RNN) {
                        __half l0 = __float2half_rn(v0 - __half2float(h0));
                        __half l1 = __float2half_rn(v1 - __half2float(h1));
                        *(__half2*)(Olo + (size_t)row * NOUT + c) = __halves2half2(l0, l1);
                    }
                }
            }
        }
    }

    if constexpr (MODE == MODE_LOSS) {
#pragma unroll
        for (int o = 16; o > 0; o >>= 1) {
            lsum += __shfl_xor_sync(0xFFFFFFFFu, lsum, o);
            msum += __shfl_xor_sync(0xFFFFFFFFu, msum, o);
        }
        if (lid == 0) { redL[wid] = lsum; redM[wid] = msum; }
        __syncthreads();
        if (tid == 0) {
            float L = 0.f, Mt = 0.f;
#pragma unroll
            for (int i = 0; i < 8; i++) { L += redL[i]; Mt += redM[i]; }
            atomicAdd(&g_loss, (double)L);
            atomicAdd(&g_totm, (double)Mt);
        }
    }
}

// ---- thin wrappers for the serial Euler GEMMs ----
template<int MODE, int KDIM, int NOUT>
__global__ __launch_bounds__(256, 2)
void mma_gemm(const __half* __restrict__ Ah,  const __half* __restrict__ Bh,
              const float* __restrict__ bias,
              const __half* __restrict__ Cin_hi, const __half* __restrict__ Cin_lo,
              __half* __restrict__ Ohi, __half* __restrict__ Olo)
{
    gemm_body<MODE, KDIM, NOUT>(Ah, Bh, nullptr, nullptr, bias, nullptr,
                                Cin_hi, Cin_lo, Ohi, Olo, nullptr, nullptr, nullptr);
}

// ---- fused launch A: z=0 RELU_G, z=1 RNN (independent).
//      Last obs step launches with gridDim.z==1 -> RNN (dead work) skipped. ----
__global__ __launch_bounds__(256, 2)
void obs_a_kernel(const __half* __restrict__ h_hi,
                  const __half* __restrict__ Wp1h, const float* __restrict__ bp1,
                  __half* __restrict__ p1_hi,
                  const __half* __restrict__ Xhs,
                  const __half* __restrict__ Wih, const __half* __restrict__ Whh,
                  const float* __restrict__ b_ih, const float* __restrict__ b_hh,
                  __half* __restrict__ hn_hi, __half* __restrict__ hn_lo,
                  const int* __restrict__ is)
{
    if (blockIdx.z == 0)
        gemm_body<MODE_RELU_G, HID, HID>(h_hi, Wp1h, nullptr, nullptr, bp1, nullptr,
                                         nullptr, nullptr, p1_hi, nullptr, is, nullptr, nullptr);
    else
        gemm_body<MODE_RNN, 640, HID>(Xhs, Wih, h_hi, Whh, b_ih, b_hh,
                                      nullptr, nullptr, hn_hi, hn_lo, is, nullptr, nullptr);
}

// ---- fused launch B: z=0 LOSS (x==0 only), z=1 scatter (128 CTAs, full MLP).
//      Last obs step launches with grid (1,32,1) -> scatter (dead work) skipped. ----
__global__ __launch_bounds__(256, 2)
void obs_b_kernel(const __half* __restrict__ p1_hi,
                  const __half* __restrict__ Wp2h, const float* __restrict__ bp2,
                  const float* __restrict__ Xs, const float* __restrict__ Ms,
                  const int* __restrict__ is)
{
    if (blockIdx.z == 0) {
        if (blockIdx.x != 0) return;   // LOSS has a single col-tile (DIN=128)
        gemm_body<MODE_LOSS, HID, DIN>(p1_hi, Wp2h, nullptr, nullptr, bp2, nullptr,
                                       nullptr, nullptr, nullptr, nullptr, nullptr, Xs, Ms);
    } else {
        // scatter: 128 CTAs (x:4 * y:32), 32 rows each; 16 uint4 stores/thread
        const int tid = threadIdx.x;
        const int rowbase = (blockIdx.y * 4 + blockIdx.x) * 32;
#pragma unroll 1
        for (int i = tid; i < 32 * 64; i += 256) {
            int r = i >> 6, q = i & 63;
            size_t dst = (size_t)is[rowbase + r] * HID;
            size_t src = (size_t)(rowbase + r) * HID;
            ((uint4*)(g_h_hi + dst))[q] = ((const uint4*)(g_hn_hi + src))[q];
            ((uint4*)(g_h_lo + dst))[q] = ((const uint4*)(g_hn_lo + src))[q];
        }
    }
}

// ------------------------------------------------------------------
// Small kernels
// ------------------------------------------------------------------
__global__ void init_kernel()
{
    size_t i = (size_t)blockIdx.x * blockDim.x + threadIdx.x;   // over NSAMP*HID/8
    ((uint4*)g_h_hi)[i] = make_uint4(0, 0, 0, 0);
    ((uint4*)g_h_lo)[i] = make_uint4(0, 0, 0, 0);
    if (i == 0) { g_loss = 0.0; g_totm = 0.0; }
}

__global__ void conv_hi_kernel(const float* __restrict__ src,
                               __half* __restrict__ hi, int n4)
{
    int i = blockIdx.x * blockDim.x + threadIdx.x;
    if (i >= n4) return;
    float4 s = ((const float4*)src)[i];
    ((__half2*)hi)[i * 2]     = __halves2half2(__float2half_rn(s.x), __float2half_rn(s.y));
    ((__half2*)hi)[i * 2 + 1] = __halves2half2(__float2half_rn(s.z), __float2half_rn(s.w));
}

// all 6 weight conversions in ONE kernel
__global__ void conv_weights_kernel(const float* __restrict__ W_ih, const float* __restrict__ W_hh,
                                    const float* __restrict__ Wo1,  const float* __restrict__ Wo2,
                                    const float* __restrict__ Wp1,  const float* __restrict__ Wp2)
{
    int i = blockIdx.x * blockDim.x + threadIdx.x;   // float4 index, total 294912
    const float* src; __half* dst; int base;
    if      (i <  16384) { src = W_ih; dst = g_Wih_h; base = 0;      }
    else if (i <  81920) { src = W_hh; dst = g_Whh_h; base = 16384;  }
    else if (i < 147456) { src = Wo1;  dst = g_Wo1_h; base = 81920;  }
    else if (i < 212992) { src = Wo2;  dst = g_Wo2_h; base = 147456; }
    else if (i < 278528) { src = Wp1;  dst = g_Wp1_h; base = 212992; }
    else if (i < 294912) { src = Wp2;  dst = g_Wp2_h; base = 278528; }
    else return;
    int j = i - base;
    float4 s = ((const float4*)src)[j];
    ((__half2*)dst)[j * 2]     = __halves2half2(__float2half_rn(s.x), __float2half_rn(s.y));
    ((__half2*)dst)[j * 2 + 1] = __halves2half2(__float2half_rn(s.z), __float2half_rn(s.w));
}

__global__ void final_kernel(float* __restrict__ out)
{
    out[0] = (float)g_loss;
    out[1] = (float)(g_loss / g_totm);
}

// ------------------------------------------------------------------
// Launch
// ------------------------------------------------------------------
extern "C" void kernel_launch(void* const* d_in, const int* in_sizes, int n_in,
                              void* d_out, int out_size)
{
    const float* X    = (const float*)d_in[0];
    const float* Mm   = (const float*)d_in[1];
    const int*   bidx = (const int*)  d_in[2];
    const float* W_ih = (const float*)d_in[3];
    const float* b_ih = (const float*)d_in[4];
    const float* W_hh = (const float*)d_in[5];
    const float* b_hh = (const float*)d_in[6];
    const float* Wo1  = (const float*)d_in[7];
    const float* bo1  = (const float*)d_in[8];
    const float* Wo2  = (const float*)d_in[9];
    const float* bo2  = (const float*)d_in[10];
    const float* Wp1  = (const float*)d_in[11];
    const float* bp1  = (const float*)d_in[12];
    const float* Wp2  = (const float*)d_in[13];
    const float* bp2  = (const float*)d_in[14];

    __half *h_hi, *h_lo, *t_hi, *p1_hi, *hn_hi, *hn_lo, *X_hi;
    __half *Wih, *Whh, *Wo1h, *Wo2h, *Wp1h, *Wp2h;
    cudaGetSymbolAddress((void**)&h_hi,  g_h_hi);   cudaGetSymbolAddress((void**)&h_lo,  g_h_lo);
    cudaGetSymbolAddress((void**)&t_hi,  g_t_hi);
    cudaGetSymbolAddress((void**)&p1_hi, g_p1_hi);
    cudaGetSymbolAddress((void**)&hn_hi, g_hn_hi);  cudaGetSymbolAddress((void**)&hn_lo, g_hn_lo);
    cudaGetSymbolAddress((void**)&X_hi,  g_X_hi);
    cudaGetSymbolAddress((void**)&Wih,  g_Wih_h);
    cudaGetSymbolAddress((void**)&Whh,  g_Whh_h);
    cudaGetSymbolAddress((void**)&Wo1h, g_Wo1_h);
    cudaGetSymbolAddress((void**)&Wo2h, g_Wo2_h);
    cudaGetSymbolAddress((void**)&Wp1h, g_Wp1_h);
    cudaGetSymbolAddress((void**)&Wp2h, g_Wp2_h);

    cudaFuncSetAttribute(mma_gemm<MODE_TANH,   HID, HID>, cudaFuncAttributeMaxDynamicSharedMemorySize, SMEM_DYN);
    cudaFuncSetAttribute(mma_gemm<MODE_EULER,  HID, HID>, cudaFuncAttributeMaxDynamicSharedMemorySize, SMEM_DYN);
    cudaFuncSetAttribute(obs_a_kernel, cudaFuncAttributeMaxDynamicSharedMemorySize, SMEM_DYN);
    cudaFuncSetAttribute(obs_b_kernel, cudaFuncAttributeMaxDynamicSharedMemorySize, SMEM_DYN);

    // launch 0: zero state + accumulators
    init_kernel<<<(NSAMP * HID / 8) / 256, 256>>>();
    // launch 1: convert X
    conv_hi_kernel<<<(KOBS*EOBS*DIN/4 + 255)/256, 256>>>(X, X_hi, KOBS*EOBS*DIN/4);
    // launch 2: convert all 6 weight matrices
    conv_weights_kernel<<<1152, 256>>>(W_ih, W_hh, Wo1, Wo2, Wp1, Wp2);

    const dim3 gEuler(HID / 128, NSAMP / 128);      // (4, 128)
    const dim3 gObsA (HID / 128, EOBS  / 128, 2);   // (4, 32, 2): RELU_G || RNN
    const dim3 gObsAL(HID / 128, EOBS  / 128, 1);   // last step: RELU_G only
    const dim3 gObsB (4,         EOBS  / 128, 2);   // (4, 32, 2): LOSS(x==0) || scatter
    const dim3 gObsBL(1,         EOBS  / 128, 1);   // last step: LOSS only

    for (int s = 0; s < KOBS; s++) {
        const float* Xs = X  + (size_t)s * EOBS * DIN;
        const float* Ms = Mm + (size_t)s * EOBS * DIN;
        const int*   is = bidx + (size_t)s * EOBS;
        const __half* Xhs = X_hi + (size_t)s * EOBS * DIN;
        const bool last = (s == KOBS - 1);

        for (int e = 0; e < 2; e++) {
            // t = tanh(h_hi @ Wo1^T + bo1)    (launch 5 in step 0 -> ncu lands here)
            mma_gemm<MODE_TANH, HID, HID><<<gEuler, 256, SMEM_DYN>>>(
                h_hi, Wo1h, bo1, nullptr, nullptr, t_hi, nullptr);
            // h = (h_hi+h_lo) + DT*(t @ Wo2^T + bo2)   (state kept hi+lo)
            mma_gemm<MODE_EULER, HID, HID><<<gEuler, 256, SMEM_DYN>>>(
                t_hi, Wo2h, bo2, h_hi, h_lo, h_hi, h_lo);
        }
        // RELU_G || RNN  (RNN dead on last step -> z-extent 1)
        obs_a_kernel<<<last ? gObsAL : gObsA, 256, SMEM_DYN>>>(
            h_hi, Wp1h, bp1, p1_hi, Xhs, Wih, Whh, b_ih, b_hh, hn_hi, hn_lo, is);
        // LOSS || scatter  (scatter dead on last step -> grid (1,32,1))
        obs_b_kernel<<<last ? gObsBL : gObsB, 256, SMEM_DYN>>>(p1_hi, Wp2h, bp2, Xs, Ms, is);
    }
    // prop_to_end Euler steps are output-invariant -> skipped.

    final_kernel<<<1, 1>>>((float*)d_out);
}